// round 1
// baseline (speedup 1.0000x reference)
#include <cuda_runtime.h>

#define BB 4
#define NN 8192
#define DD 1024
#define HH 8
#define DK 128
#define BN (BB*NN)
#define SPLITS 16
#define CH (NN/SPLITS)
#define EPSF 1e-5f

// Scratch (allocation-free: device globals)
__device__ float g_Kn[(size_t)BB*HH*NN*DK];            // normalized K, [B,H,N,dk]
__device__ float g_Vn[(size_t)BB*HH*NN*DK];            // normalized V
__device__ float g_Spart[(size_t)SPLITS*BB*HH*DK*DK];  // score partials
__device__ float g_Weff[(size_t)BB*DD*DD];             // Wq^T @ P per batch
__device__ float g_beff[(size_t)BB*DD];                // bq @ P per batch

// ---------------------------------------------------------------------------
// Kernel A: Y = X @ W^T + b, then per-head LayerNorm over dk=128, write
// [B,H,N,dk]. One block computes a 64-row x 128-col (one head) tile.
// ---------------------------------------------------------------------------
__global__ __launch_bounds__(256)
void proj_ln_kernel(const float* __restrict__ X, const float* __restrict__ W,
                    const float* __restrict__ bias,
                    const float* __restrict__ gamma, const float* __restrict__ beta,
                    int sel)
{
    __shared__ float Xs[16][64];
    __shared__ float Ws[16][128];

    float* __restrict__ out = sel ? g_Vn : g_Kn;

    const int h  = blockIdx.y;
    const int r0 = blockIdx.x * 64;
    const int tid = threadIdx.x;
    const int ty = tid >> 4, tx = tid & 15;

    float acc[4][8];
    #pragma unroll
    for (int i = 0; i < 4; i++)
        #pragma unroll
        for (int j = 0; j < 8; j++) acc[i][j] = 0.f;

    const int xr = tid >> 2;          // X load: row 0..63
    const int xc = (tid & 3) * 4;     // X load: 4 cols of 16
    const int wc = tid >> 1;          // W load: col 0..127
    const int wk = (tid & 1) * 8;     // W load: k-half

    for (int c0 = 0; c0 < DD; c0 += 16) {
        float4 xv = *(const float4*)&X[(size_t)(r0 + xr) * DD + c0 + xc];
        Xs[xc + 0][xr] = xv.x; Xs[xc + 1][xr] = xv.y;
        Xs[xc + 2][xr] = xv.z; Xs[xc + 3][xr] = xv.w;

        const float* wp = &W[(size_t)(h * DK + wc) * DD + c0 + wk];
        float4 w0 = *(const float4*)wp;
        float4 w1 = *(const float4*)(wp + 4);
        Ws[wk + 0][wc] = w0.x; Ws[wk + 1][wc] = w0.y;
        Ws[wk + 2][wc] = w0.z; Ws[wk + 3][wc] = w0.w;
        Ws[wk + 4][wc] = w1.x; Ws[wk + 5][wc] = w1.y;
        Ws[wk + 6][wc] = w1.z; Ws[wk + 7][wc] = w1.w;
        __syncthreads();

        #pragma unroll
        for (int kk = 0; kk < 16; kk++) {
            float a[4], b[8];
            *(float4*)a       = *(const float4*)&Xs[kk][ty * 4];
            *(float4*)b       = *(const float4*)&Ws[kk][tx * 8];
            *(float4*)(b + 4) = *(const float4*)&Ws[kk][tx * 8 + 4];
            #pragma unroll
            for (int i = 0; i < 4; i++)
                #pragma unroll
                for (int j = 0; j < 8; j++) acc[i][j] += a[i] * b[j];
        }
        __syncthreads();
    }

    // epilogue: bias + per-row LayerNorm over 128 cols (16 lanes x 8 each)
    float bj[8], gj[8], ej[8];
    #pragma unroll
    for (int j = 0; j < 8; j++) {
        int col = tx * 8 + j;
        bj[j] = bias[h * DK + col];
        gj[j] = gamma[h * DK + col];
        ej[j] = beta[h * DK + col];
    }

    #pragma unroll
    for (int i = 0; i < 4; i++) {
        float s = 0.f, ss = 0.f;
        #pragma unroll
        for (int j = 0; j < 8; j++) {
            float v = acc[i][j] + bj[j];
            acc[i][j] = v;
            s += v; ss += v * v;
        }
        #pragma unroll
        for (int o = 8; o >= 1; o >>= 1) {
            s  += __shfl_xor_sync(0xFFFFFFFFu, s,  o, 16);
            ss += __shfl_xor_sync(0xFFFFFFFFu, ss, o, 16);
        }
        float mean = s * (1.f / DK);
        float var  = ss * (1.f / DK) - mean * mean;
        float inv  = rsqrtf(var + EPSF);

        int r  = r0 + ty * 4 + i;
        int b_ = r >> 13;
        int n_ = r & (NN - 1);
        size_t obase = (((size_t)(b_ * HH + h)) * NN + n_) * DK + tx * 8;
        float o[8];
        #pragma unroll
        for (int j = 0; j < 8; j++)
            o[j] = (acc[i][j] - mean) * inv * gj[j] + ej[j];
        *(float4*)&out[obase]     = *(float4*)o;
        *(float4*)&out[obase + 4] = *(float4*)(o + 4);
    }
}

// ---------------------------------------------------------------------------
// Kernel B: score partials. partial[d][e] = sum_{n in chunk} Kn[n,d]*Vn[n,e]
// ---------------------------------------------------------------------------
__global__ __launch_bounds__(256)
void scores_kernel()
{
    const int split = blockIdx.x;
    const int bh    = blockIdx.y;
    const int tid = threadIdx.x;
    const int ty = tid >> 4, tx = tid & 15;

    __shared__ float Ks[16][128];
    __shared__ float Vs[16][128];

    float acc[8][8];
    #pragma unroll
    for (int i = 0; i < 8; i++)
        #pragma unroll
        for (int j = 0; j < 8; j++) acc[i][j] = 0.f;

    const size_t base = (size_t)bh * NN * DK + (size_t)split * CH * DK;
    const int ln = tid >> 4;
    const int ld = (tid & 15) * 8;

    for (int n0 = 0; n0 < CH; n0 += 16) {
        const float* kp = &g_Kn[base + (size_t)(n0 + ln) * DK + ld];
        const float* vp = &g_Vn[base + (size_t)(n0 + ln) * DK + ld];
        *(float4*)&Ks[ln][ld]     = *(const float4*)kp;
        *(float4*)&Ks[ln][ld + 4] = *(const float4*)(kp + 4);
        *(float4*)&Vs[ln][ld]     = *(const float4*)vp;
        *(float4*)&Vs[ln][ld + 4] = *(const float4*)(vp + 4);
        __syncthreads();

        #pragma unroll
        for (int nn = 0; nn < 16; nn++) {
            float a[8], b[8];
            *(float4*)a       = *(const float4*)&Ks[nn][ty * 8];
            *(float4*)(a + 4) = *(const float4*)&Ks[nn][ty * 8 + 4];
            *(float4*)b       = *(const float4*)&Vs[nn][tx * 8];
            *(float4*)(b + 4) = *(const float4*)&Vs[nn][tx * 8 + 4];
            #pragma unroll
            for (int i = 0; i < 8; i++)
                #pragma unroll
                for (int j = 0; j < 8; j++) acc[i][j] += a[i] * b[j];
        }
        __syncthreads();
    }

    size_t pbase = ((size_t)split * (BB * HH) + bh) * DK * DK;
    #pragma unroll
    for (int i = 0; i < 8; i++) {
        size_t ro = pbase + (size_t)(ty * 8 + i) * DK + tx * 8;
        *(float4*)&g_Spart[ro]     = *(float4*)&acc[i][0];
        *(float4*)&g_Spart[ro + 4] = *(float4*)&acc[i][4];
    }
}

// ---------------------------------------------------------------------------
// Kernel C: reduce partials, scale by 1/N, write p_attn to output tail
// ---------------------------------------------------------------------------
__global__ void reduce_scores_kernel(float* __restrict__ p_out)
{
    int i = blockIdx.x * 256 + threadIdx.x;  // < B*H*DK*DK
    float s = 0.f;
    #pragma unroll
    for (int sp = 0; sp < SPLITS; sp++)
        s += g_Spart[(size_t)sp * (BB * HH * DK * DK) + i];
    p_out[i] = s * (1.f / NN);
}

// ---------------------------------------------------------------------------
// Kernel: beff[b, h*128+e] = sum_d bq[h*128+d] * P[b,h,d,e]
// ---------------------------------------------------------------------------
__global__ void beff_kernel(const float* __restrict__ bq, const float* __restrict__ p)
{
    int bh = blockIdx.x;
    int e  = threadIdx.x;
    int h  = bh & (HH - 1), b_ = bh >> 3;
    const float* pp = p + (size_t)bh * DK * DK;
    float s = 0.f;
    #pragma unroll 8
    for (int d = 0; d < DK; d++) s += bq[h * DK + d] * pp[(size_t)d * DK + e];
    g_beff[(size_t)b_ * DD + h * DK + e] = s;
}

// ---------------------------------------------------------------------------
// Kernel D: Weff[b][c][h*128+e] = sum_d Wq[h*128+d][c] * P[b,h,d,e]
// ---------------------------------------------------------------------------
__global__ __launch_bounds__(256)
void weff_kernel(const float* __restrict__ Wq, const float* __restrict__ p)
{
    const int c0 = blockIdx.x * 64;
    const int bh = blockIdx.y;
    const int h = bh & (HH - 1), b_ = bh >> 3;
    const int tid = threadIdx.x;
    const int ty = tid >> 4, tx = tid & 15;

    __shared__ float As[16][64];
    __shared__ float Bs[16][128];

    float acc[4][8];
    #pragma unroll
    for (int i = 0; i < 4; i++)
        #pragma unroll
        for (int j = 0; j < 8; j++) acc[i][j] = 0.f;

    const int ak = tid >> 4;
    const int ar = (tid & 15) * 4;
    const int bk = tid >> 4;
    const int bc = (tid & 15) * 8;

    for (int k0 = 0; k0 < DK; k0 += 16) {
        *(float4*)&As[ak][ar] =
            *(const float4*)&Wq[(size_t)(h * DK + k0 + ak) * DD + c0 + ar];
        const float* pp = &p[(size_t)bh * DK * DK + (size_t)(k0 + bk) * DK + bc];
        *(float4*)&Bs[bk][bc]     = *(const float4*)pp;
        *(float4*)&Bs[bk][bc + 4] = *(const float4*)(pp + 4);
        __syncthreads();

        #pragma unroll
        for (int kk = 0; kk < 16; kk++) {
            float a[4], b[8];
            *(float4*)a       = *(const float4*)&As[kk][ty * 4];
            *(float4*)b       = *(const float4*)&Bs[kk][tx * 8];
            *(float4*)(b + 4) = *(const float4*)&Bs[kk][tx * 8 + 4];
            #pragma unroll
            for (int i = 0; i < 4; i++)
                #pragma unroll
                for (int j = 0; j < 8; j++) acc[i][j] += a[i] * b[j];
        }
        __syncthreads();
    }

    #pragma unroll
    for (int i = 0; i < 4; i++) {
        size_t ro = (size_t)b_ * DD * DD + (size_t)(c0 + ty * 4 + i) * DD
                    + h * DK + tx * 8;
        *(float4*)&g_Weff[ro]     = *(float4*)&acc[i][0];
        *(float4*)&g_Weff[ro + 4] = *(float4*)&acc[i][4];
    }
}

// ---------------------------------------------------------------------------
// Kernel E: att[b,n,:] = query[b,n,:] @ Weff[b] + beff[b]
// ---------------------------------------------------------------------------
__global__ __launch_bounds__(256)
void final_gemm_kernel(const float* __restrict__ Q, float* __restrict__ outp)
{
    const int r0 = blockIdx.x * 64;
    const int j0 = blockIdx.y * 128;
    const int b_ = r0 >> 13;
    const int tid = threadIdx.x;
    const int ty = tid >> 4, tx = tid & 15;

    __shared__ float Xs[16][64];
    __shared__ float Ws[16][128];

    float acc[4][8];
    #pragma unroll
    for (int i = 0; i < 4; i++)
        #pragma unroll
        for (int j = 0; j < 8; j++) acc[i][j] = 0.f;

    const int xr = tid >> 2;
    const int xc = (tid & 3) * 4;
    const int wk = tid >> 4;
    const int wcol = (tid & 15) * 8;

    for (int c0 = 0; c0 < DD; c0 += 16) {
        float4 xv = *(const float4*)&Q[(size_t)(r0 + xr) * DD + c0 + xc];
        Xs[xc + 0][xr] = xv.x; Xs[xc + 1][xr] = xv.y;
        Xs[xc + 2][xr] = xv.z; Xs[xc + 3][xr] = xv.w;

        const float* wp = &g_Weff[(size_t)b_ * DD * DD + (size_t)(c0 + wk) * DD + j0 + wcol];
        *(float4*)&Ws[wk][wcol]     = *(const float4*)wp;
        *(float4*)&Ws[wk][wcol + 4] = *(const float4*)(wp + 4);
        __syncthreads();

        #pragma unroll
        for (int kk = 0; kk < 16; kk++) {
            float a[4], b[8];
            *(float4*)a       = *(const float4*)&Xs[kk][ty * 4];
            *(float4*)b       = *(const float4*)&Ws[kk][tx * 8];
            *(float4*)(b + 4) = *(const float4*)&Ws[kk][tx * 8 + 4];
            #pragma unroll
            for (int i = 0; i < 4; i++)
                #pragma unroll
                for (int j = 0; j < 8; j++) acc[i][j] += a[i] * b[j];
        }
        __syncthreads();
    }

    #pragma unroll
    for (int i = 0; i < 4; i++) {
        int r = r0 + ty * 4 + i;
        float o[8];
        #pragma unroll
        for (int j = 0; j < 8; j++)
            o[j] = acc[i][j] + g_beff[(size_t)b_ * DD + j0 + tx * 8 + j];
        size_t ro = (size_t)r * DD + j0 + tx * 8;
        *(float4*)&outp[ro]     = *(float4*)o;
        *(float4*)&outp[ro + 4] = *(float4*)(o + 4);
    }
}

extern "C" void kernel_launch(void* const* d_in, const int* in_sizes, int n_in,
                              void* d_out, int out_size)
{
    const float* q   = (const float*)d_in[0];
    const float* k   = (const float*)d_in[1];
    const float* v   = (const float*)d_in[2];
    const float* Wq  = (const float*)d_in[3];
    const float* bq  = (const float*)d_in[4];
    const float* Wk  = (const float*)d_in[5];
    const float* bk  = (const float*)d_in[6];
    const float* Wv  = (const float*)d_in[7];
    const float* bv  = (const float*)d_in[8];
    const float* gK  = (const float*)d_in[9];
    const float* beK = (const float*)d_in[10];
    const float* gV  = (const float*)d_in[11];
    const float* beV = (const float*)d_in[12];

    float* out   = (float*)d_out;
    float* p_out = out + (size_t)BN * DD;   // p_attn tail

    dim3 blk(256);

    proj_ln_kernel<<<dim3(BN / 64, HH), blk>>>(k, Wk, bk, gK, beK, 0);
    proj_ln_kernel<<<dim3(BN / 64, HH), blk>>>(v, Wv, bv, gV, beV, 1);
    scores_kernel<<<dim3(SPLITS, BB * HH), blk>>>();
    reduce_scores_kernel<<<dim3((BB * HH * DK * DK) / 256), blk>>>(p_out);
    beff_kernel<<<dim3(BB * HH), dim3(DK)>>>(bq, p_out);
    weff_kernel<<<dim3(DD / 64, BB * HH), blk>>>(Wq, p_out);
    final_gemm_kernel<<<dim3(BN / 64, DD / 128), blk>>>(q, out);
}

// round 3
// speedup vs baseline: 4.9347x; 4.9347x over previous
#include <cuda_runtime.h>
#include <cstdint>

#define BB 4
#define NN 8192
#define DD 1024
#define HH 8
#define DK 128
#define BN (BB*NN)
#define SPLITS 8
#define CHS (NN/SPLITS)        // 1024 rows per scores split
#define EPSF 1e-5f

#define NKC (DD/32)            // 32 k-chunks for the big GEMMs

// Scratch (allocation-free: device globals)
__device__ float g_Kn[(size_t)BB*HH*NN*DK];
__device__ float g_Vn[(size_t)BB*HH*NN*DK];
__device__ float g_Spart[(size_t)SPLITS*BB*HH*DK*DK];
__device__ float g_WeffT[(size_t)BB*DD*DD];   // [b][e'][c] (rows K-major over c)
__device__ float g_beff[(size_t)BB*DD];

// ---------------------------------------------------------------------------
// helpers
// ---------------------------------------------------------------------------
__device__ __forceinline__ uint32_t smem_u32(const void* p) {
    uint32_t a;
    asm("{ .reg .u64 t; cvta.to.shared.u64 t, %1; cvt.u32.u64 %0, t; }"
        : "=r"(a) : "l"(p));
    return a;
}
__device__ __forceinline__ void cp16(uint32_t smem, const void* g) {
    asm volatile("cp.async.cg.shared.global [%0], [%1], 16;"
                 :: "r"(smem), "l"(g));
}
#define CP_COMMIT() asm volatile("cp.async.commit_group;" ::: "memory")
#define CP_WAIT(n)  asm volatile("cp.async.wait_group %0;" :: "n"(n) : "memory")

__device__ __forceinline__ uint32_t f2tf(float x) {
    uint32_t r;
    asm("cvt.rna.tf32.f32 %0, %1;" : "=r"(r) : "f"(x));
    return r;
}
__device__ __forceinline__ void mma8(float* d, const uint32_t* a, const uint32_t* b) {
    asm volatile(
        "mma.sync.aligned.m16n8k8.row.col.f32.tf32.tf32.f32 "
        "{%0,%1,%2,%3}, {%4,%5,%6,%7}, {%8,%9}, {%0,%1,%2,%3};"
        : "+f"(d[0]), "+f"(d[1]), "+f"(d[2]), "+f"(d[3])
        : "r"(a[0]), "r"(a[1]), "r"(a[2]), "r"(a[3]), "r"(b[0]), "r"(b[1]));
}

// ---------------------------------------------------------------------------
// Big GEMM on mma.sync tf32.
//   C[128,128] tile of A[BN,1024] @ B^T  (B rows K-major, 1024 long)
// mode 0: B=Wk head jb, epilogue bias+LN -> g_Kn
// mode 1: B=Wv head jb, epilogue bias+LN -> g_Vn
// mode 2: B=g_WeffT[b] block jb, epilogue + g_beff -> out
// smem: 2 stages x (A[128][40] + B[128][40]) floats = 81920 B
// ---------------------------------------------------------------------------
__global__ __launch_bounds__(256)
void gemm_mma(const float* __restrict__ A, const float* __restrict__ Bmat,
              const float* __restrict__ bias, const float* __restrict__ gamma,
              const float* __restrict__ beta, float* __restrict__ outp, int mode)
{
    extern __shared__ float sm[];
    const int r0  = blockIdx.x * 128;
    const int jb  = blockIdx.y;
    const int b_  = r0 >> 13;
    const int tid = threadIdx.x;
    const int warp = tid >> 5, lane = tid & 31;
    const int wm = warp >> 1, wn = warp & 1;
    const int gid = lane >> 2, tig = lane & 3;

    const float* Ap = A + (size_t)r0 * DD;
    const float* Bp = (mode == 2)
        ? (g_WeffT + (size_t)b_ * DD * DD + (size_t)jb * DK * DD)
        : (Bmat + (size_t)jb * DK * DD);

    const uint32_t smb = smem_u32(sm);

    float acc[2][8][4];
    #pragma unroll
    for (int mt = 0; mt < 2; mt++)
        #pragma unroll
        for (int nt = 0; nt < 8; nt++)
            #pragma unroll
            for (int i = 0; i < 4; i++) acc[mt][nt][i] = 0.f;

    // stage layout (bytes): A at s*40960, B at s*40960 + 20480; row stride 160B
    auto load_stage = [&](int kc, int s) {
        uint32_t ab = smb + (uint32_t)s * 40960u;
        const float* ga = Ap + kc * 32;
        const float* gb = Bp + kc * 32;
        #pragma unroll
        for (int u = 0; u < 4; u++) {
            int idx = u * 256 + tid;
            int row = idx >> 3, ch = idx & 7;
            uint32_t off = (uint32_t)(row * 160 + ch * 16);
            cp16(ab + off,          ga + (size_t)row * DD + ch * 4);
            cp16(ab + 20480u + off, gb + (size_t)row * DD + ch * 4);
        }
        CP_COMMIT();
    };

    load_stage(0, 0);

    for (int kc = 0; kc < NKC; kc++) {
        if (kc + 1 < NKC) { load_stage(kc + 1, (kc + 1) & 1); CP_WAIT(1); }
        else              { CP_WAIT(0); }
        __syncthreads();

        const float* as = sm + (kc & 1) * 10240;
        const float* bs = as + 5120;
        #pragma unroll
        for (int ks = 0; ks < 4; ks++) {
            const int k0 = ks * 8;
            uint32_t af[2][4];
            #pragma unroll
            for (int mt = 0; mt < 2; mt++) {
                const float* ap = as + (wm * 32 + mt * 16 + gid) * 40 + k0 + tig;
                af[mt][0] = f2tf(ap[0]);
                af[mt][1] = f2tf(ap[8 * 40]);
                af[mt][2] = f2tf(ap[4]);
                af[mt][3] = f2tf(ap[8 * 40 + 4]);
            }
            #pragma unroll
            for (int nt = 0; nt < 8; nt++) {
                const float* bp = bs + (wn * 64 + nt * 8 + gid) * 40 + k0 + tig;
                uint32_t bb[2] = { f2tf(bp[0]), f2tf(bp[4]) };
                mma8(acc[0][nt], af[0], bb);
                mma8(acc[1][nt], af[1], bb);
            }
        }
        __syncthreads();
    }

    if (mode == 2) {
        float2 bev[8];
        #pragma unroll
        for (int nt = 0; nt < 8; nt++)
            bev[nt] = *(const float2*)&g_beff[(size_t)b_ * DD + jb * DK
                                              + wn * 64 + nt * 8 + tig * 2];
        #pragma unroll
        for (int mt = 0; mt < 2; mt++)
            #pragma unroll
            for (int h = 0; h < 2; h++) {
                int row = wm * 32 + mt * 16 + gid + h * 8;
                float* op = outp + (size_t)(r0 + row) * DD + jb * DK;
                #pragma unroll
                for (int nt = 0; nt < 8; nt++) {
                    float2 o;
                    o.x = acc[mt][nt][2 * h + 0] + bev[nt].x;
                    o.y = acc[mt][nt][2 * h + 1] + bev[nt].y;
                    *(float2*)(op + wn * 64 + nt * 8 + tig * 2) = o;
                }
            }
        return;
    }

    // mode 0/1: bias + per-row LayerNorm over 128 cols, write [B,H,N,dk]
    float2 bv[8], gv[8], ev[8];
    #pragma unroll
    for (int nt = 0; nt < 8; nt++) {
        int c = jb * DK + wn * 64 + nt * 8 + tig * 2;
        bv[nt] = *(const float2*)&bias[c];
        gv[nt] = *(const float2*)&gamma[c];
        ev[nt] = *(const float2*)&beta[c];
    }
    float s_[2][2], ss_[2][2];
    #pragma unroll
    for (int mt = 0; mt < 2; mt++)
        #pragma unroll
        for (int h = 0; h < 2; h++) { s_[mt][h] = 0.f; ss_[mt][h] = 0.f; }

    #pragma unroll
    for (int mt = 0; mt < 2; mt++)
        #pragma unroll
        for (int nt = 0; nt < 8; nt++) {
            acc[mt][nt][0] += bv[nt].x; acc[mt][nt][1] += bv[nt].y;
            acc[mt][nt][2] += bv[nt].x; acc[mt][nt][3] += bv[nt].y;
            #pragma unroll
            for (int h = 0; h < 2; h++) {
                float x0 = acc[mt][nt][2 * h], x1 = acc[mt][nt][2 * h + 1];
                s_[mt][h]  += x0 + x1;
                ss_[mt][h] += x0 * x0 + x1 * x1;
            }
        }
    #pragma unroll
    for (int mt = 0; mt < 2; mt++)
        #pragma unroll
        for (int h = 0; h < 2; h++) {
            #pragma unroll
            for (int o = 1; o <= 2; o <<= 1) {
                s_[mt][h]  += __shfl_xor_sync(0xFFFFFFFFu, s_[mt][h],  o);
                ss_[mt][h] += __shfl_xor_sync(0xFFFFFFFFu, ss_[mt][h], o);
            }
        }

    float* red = sm;   // [row][wn][2], 512 floats; stages fully consumed
    if (tig == 0) {
        #pragma unroll
        for (int mt = 0; mt < 2; mt++)
            #pragma unroll
            for (int h = 0; h < 2; h++) {
                int row = wm * 32 + mt * 16 + gid + h * 8;
                red[(row * 2 + wn) * 2 + 0] = s_[mt][h];
                red[(row * 2 + wn) * 2 + 1] = ss_[mt][h];
            }
    }
    __syncthreads();

    float* dst = mode ? g_Vn : g_Kn;
    #pragma unroll
    for (int mt = 0; mt < 2; mt++)
        #pragma unroll
        for (int h = 0; h < 2; h++) {
            int row = wm * 32 + mt * 16 + gid + h * 8;
            float st  = red[(row * 2 + 0) * 2 + 0] + red[(row * 2 + 1) * 2 + 0];
            float sst = red[(row * 2 + 0) * 2 + 1] + red[(row * 2 + 1) * 2 + 1];
            float mean = st * (1.f / DK);
            float var  = sst * (1.f / DK) - mean * mean;
            float inv  = rsqrtf(var + EPSF);
            int r  = r0 + row;
            float* op = dst + (((size_t)(b_ * HH + jb)) * NN + (r & (NN - 1))) * DK;
            #pragma unroll
            for (int nt = 0; nt < 8; nt++) {
                float2 o;
                o.x = (acc[mt][nt][2 * h + 0] - mean) * inv * gv[nt].x + ev[nt].x;
                o.y = (acc[mt][nt][2 * h + 1] - mean) * inv * gv[nt].y + ev[nt].y;
                *(float2*)(op + wn * 64 + nt * 8 + tig * 2) = o;
            }
        }
}

// ---------------------------------------------------------------------------
// scores on mma.sync tf32: partial[d][e] = sum_{n in split} Kn[n,d]*Vn[n,e]
// smem: 2 stages x (K[32][136] + V[32][136]) floats = 69632 B; conflict-free
// ---------------------------------------------------------------------------
__global__ __launch_bounds__(256)
void scores_mma()
{
    extern __shared__ float sm[];
    const int split = blockIdx.x;
    const int bh    = blockIdx.y;
    const int tid = threadIdx.x;
    const int warp = tid >> 5, lane = tid & 31;
    const int wm = warp >> 1, wn = warp & 1;
    const int gid = lane >> 2, tig = lane & 3;

    const size_t base = (size_t)bh * NN * DK + (size_t)split * CHS * DK;
    const uint32_t smb = smem_u32(sm);

    float acc[2][8][4];
    #pragma unroll
    for (int mt = 0; mt < 2; mt++)
        #pragma unroll
        for (int nt = 0; nt < 8; nt++)
            #pragma unroll
            for (int i = 0; i < 4; i++) acc[mt][nt][i] = 0.f;

    // stage bytes: K at s*34816, V at +17408; row stride 544B (136 floats)
    auto load_stage = [&](int kc, int s) {
        uint32_t kb = smb + (uint32_t)s * 34816u;
        const float* gk = g_Kn + base + (size_t)kc * 32 * DK;
        const float* gv = g_Vn + base + (size_t)kc * 32 * DK;
        #pragma unroll
        for (int u = 0; u < 4; u++) {
            int idx = u * 256 + tid;
            int n = idx >> 5, ch = idx & 31;
            uint32_t off = (uint32_t)(n * 544 + ch * 16);
            cp16(kb + off,          gk + (size_t)n * DK + ch * 4);
            cp16(kb + 17408u + off, gv + (size_t)n * DK + ch * 4);
        }
        CP_COMMIT();
    };

    const int NCH = CHS / 32;   // 32 chunks
    load_stage(0, 0);

    for (int kc = 0; kc < NCH; kc++) {
        if (kc + 1 < NCH) { load_stage(kc + 1, (kc + 1) & 1); CP_WAIT(1); }
        else              { CP_WAIT(0); }
        __syncthreads();

        const float* ks_ = sm + (kc & 1) * 8704;
        const float* vs_ = ks_ + 4352;
        #pragma unroll
        for (int ks = 0; ks < 4; ks++) {
            const int k0 = ks * 8;
            uint32_t af[2][4];
            #pragma unroll
            for (int mt = 0; mt < 2; mt++) {
                int m = wm * 32 + mt * 16 + gid;
                af[mt][0] = f2tf(ks_[(k0 + tig) * 136 + m]);
                af[mt][1] = f2tf(ks_[(k0 + tig) * 136 + m + 8]);
                af[mt][2] = f2tf(ks_[(k0 + tig + 4) * 136 + m]);
                af[mt][3] = f2tf(ks_[(k0 + tig + 4) * 136 + m + 8]);
            }
            #pragma unroll
            for (int nt = 0; nt < 8; nt++) {
                int n = wn * 64 + nt * 8 + gid;
                uint32_t bb[2] = { f2tf(vs_[(k0 + tig) * 136 + n]),
                                   f2tf(vs_[(k0 + tig + 4) * 136 + n]) };
                mma8(acc[0][nt], af[0], bb);
                mma8(acc[1][nt], af[1], bb);
            }
        }
        __syncthreads();
    }

    size_t pbase = ((size_t)split * (BB * HH) + bh) * DK * DK;
    #pragma unroll
    for (int mt = 0; mt < 2; mt++)
        #pragma unroll
        for (int h = 0; h < 2; h++) {
            int row = wm * 32 + mt * 16 + gid + h * 8;
            #pragma unroll
            for (int nt = 0; nt < 8; nt++) {
                float2 o;
                o.x = acc[mt][nt][2 * h + 0];
                o.y = acc[mt][nt][2 * h + 1];
                *(float2*)&g_Spart[pbase + (size_t)row * DK
                                   + wn * 64 + nt * 8 + tig * 2] = o;
            }
        }
}

__global__ void reduce_scores_kernel(float* __restrict__ p_out)
{
    int i = blockIdx.x * 256 + threadIdx.x;
    float s = 0.f;
    #pragma unroll
    for (int sp = 0; sp < SPLITS; sp++)
        s += g_Spart[(size_t)sp * (BB * HH * DK * DK) + i];
    p_out[i] = s * (1.f / NN);
}

__global__ void beff_kernel(const float* __restrict__ bq, const float* __restrict__ p)
{
    int bh = blockIdx.x;
    int e  = threadIdx.x;
    int h  = bh & (HH - 1), b_ = bh >> 3;
    const float* pp = p + (size_t)bh * DK * DK;
    float s = 0.f;
    #pragma unroll 8
    for (int d = 0; d < DK; d++) s += bq[h * DK + d] * pp[(size_t)d * DK + e];
    g_beff[(size_t)b_ * DD + h * DK + e] = s;
}

// WeffT[b][h*128+e][c] = sum_d Wq[h*128+d][c] * P[b,h,d,e]
__global__ __launch_bounds__(256)
void weff_kernel(const float* __restrict__ Wq, const float* __restrict__ p)
{
    const int c0 = blockIdx.x * 64;
    const int bh = blockIdx.y;
    const int h = bh & (HH - 1), b_ = bh >> 3;
    const int tid = threadIdx.x;
    const int ty = tid >> 4, tx = tid & 15;

    __shared__ float As[16][64];
    __shared__ float Bs[16][128];

    float acc[4][8];
    #pragma unroll
    for (int i = 0; i < 4; i++)
        #pragma unroll
        for (int j = 0; j < 8; j++) acc[i][j] = 0.f;

    const int ak = tid >> 4;
    const int ar = (tid & 15) * 4;
    const int bk = tid >> 4;
    const int bc = (tid & 15) * 8;

    for (int k0 = 0; k0 < DK; k0 += 16) {
        *(float4*)&As[ak][ar] =
            *(const float4*)&Wq[(size_t)(h * DK + k0 + ak) * DD + c0 + ar];
        const float* pp = &p[(size_t)bh * DK * DK + (size_t)(k0 + bk) * DK + bc];
        *(float4*)&Bs[bk][bc]     = *(const float4*)pp;
        *(float4*)&Bs[bk][bc + 4] = *(const float4*)(pp + 4);
        __syncthreads();

        #pragma unroll
        for (int kk = 0; kk < 16; kk++) {
            float a[4], b[8];
            *(float4*)a       = *(const float4*)&As[kk][ty * 4];
            *(float4*)b       = *(const float4*)&Bs[kk][tx * 8];
            *(float4*)(b + 4) = *(const float4*)&Bs[kk][tx * 8 + 4];
            #pragma unroll
            for (int i = 0; i < 4; i++)
                #pragma unroll
                for (int j = 0; j < 8; j++) acc[i][j] += a[i] * b[j];
        }
        __syncthreads();
    }

    #pragma unroll
    for (int i = 0; i < 4; i++)
        #pragma unroll
        for (int j = 0; j < 8; j++)
            g_WeffT[(size_t)b_ * DD * DD
                    + (size_t)(h * DK + tx * 8 + j) * DD + (c0 + ty * 4 + i)]
                = acc[i][j];
}

extern "C" void kernel_launch(void* const* d_in, const int* in_sizes, int n_in,
                              void* d_out, int out_size)
{
    const float* q   = (const float*)d_in[0];
    const float* k   = (const float*)d_in[1];
    const float* v   = (const float*)d_in[2];
    const float* Wq  = (const float*)d_in[3];
    const float* bq  = (const float*)d_in[4];
    const float* Wk  = (const float*)d_in[5];
    const float* bk  = (const float*)d_in[6];
    const float* Wv  = (const float*)d_in[7];
    const float* bv  = (const float*)d_in[8];
    const float* gK  = (const float*)d_in[9];
    const float* beK = (const float*)d_in[10];
    const float* gV  = (const float*)d_in[11];
    const float* beV = (const float*)d_in[12];

    float* out   = (float*)d_out;
    float* p_out = out + (size_t)BN * DD;

    static bool attr_done = false;
    if (!attr_done) {
        cudaFuncSetAttribute(gemm_mma, cudaFuncAttributeMaxDynamicSharedMemorySize, 81920);
        cudaFuncSetAttribute(scores_mma, cudaFuncAttributeMaxDynamicSharedMemorySize, 69632);
        attr_done = true;
    }

    dim3 gg(BN / 128, HH);
    gemm_mma<<<gg, 256, 81920>>>(k, Wk, bk, gK, beK, nullptr, 0);
    gemm_mma<<<gg, 256, 81920>>>(v, Wv, bv, gV, beV, nullptr, 1);
    scores_mma<<<dim3(SPLITS, BB * HH), 256, 69632>>>();
    reduce_scores_kernel<<<dim3((BB * HH * DK * DK) / 256), 256>>>(p_out);
    beff_kernel<<<dim3(BB * HH), dim3(DK)>>>(bq, p_out);
    weff_kernel<<<dim3(DD / 64, BB * HH), 256>>>(Wq, p_out);
    gemm_mma<<<gg, 256, 81920>>>(q, nullptr, nullptr, nullptr, nullptr, out, 2);
}

// round 4
// speedup vs baseline: 10.8702x; 2.2028x over previous
#include <cuda_runtime.h>
#include <cuda_fp16.h>
#include <cstdint>

#define BB 4
#define NN 8192
#define DD 1024
#define HH 8
#define DK 128
#define BN (BB*NN)
#define SPLITS 8
#define CHS (NN/SPLITS)
#define EPSF 1e-5f
#define NKC (DD/64)            // 16 k-chunks of 64 halves for big GEMMs

// Scratch (allocation-free device globals)
__device__ __half g_hq[(size_t)BN*DD];
__device__ __half g_hk[(size_t)BN*DD];
__device__ __half g_hv[(size_t)BN*DD];
__device__ __half g_hWk[(size_t)DD*DD];
__device__ __half g_hWv[(size_t)DD*DD];
__device__ __half g_Knh[(size_t)BB*HH*NN*DK];
__device__ __half g_Vnh[(size_t)BB*HH*NN*DK];
__device__ float  g_Spart[(size_t)SPLITS*BB*HH*DK*DK];
__device__ __half g_WeffTh[(size_t)BB*DD*DD];   // [b][e'][c], c contiguous
__device__ float  g_beff[(size_t)BB*DD];

// ---------------------------------------------------------------------------
__device__ __forceinline__ uint32_t smem_u32(const void* p) {
    uint32_t a;
    asm("{ .reg .u64 t; cvta.to.shared.u64 t, %1; cvt.u32.u64 %0, t; }"
        : "=r"(a) : "l"(p));
    return a;
}
__device__ __forceinline__ void cp16(uint32_t smem, const void* g) {
    asm volatile("cp.async.cg.shared.global [%0], [%1], 16;"
                 :: "r"(smem), "l"(g));
}
#define CP_COMMIT() asm volatile("cp.async.commit_group;" ::: "memory")
#define CP_WAIT(n)  asm volatile("cp.async.wait_group %0;" :: "n"(n) : "memory")

__device__ __forceinline__ void ldsm4(uint32_t* r, uint32_t a) {
    asm volatile("ldmatrix.sync.aligned.m8n8.x4.shared.b16 {%0,%1,%2,%3}, [%4];"
                 : "=r"(r[0]), "=r"(r[1]), "=r"(r[2]), "=r"(r[3]) : "r"(a));
}
__device__ __forceinline__ void ldsm4t(uint32_t* r, uint32_t a) {
    asm volatile("ldmatrix.sync.aligned.m8n8.x4.trans.shared.b16 {%0,%1,%2,%3}, [%4];"
                 : "=r"(r[0]), "=r"(r[1]), "=r"(r[2]), "=r"(r[3]) : "r"(a));
}
__device__ __forceinline__ void mma16(float* d, const uint32_t* a, const uint32_t* b) {
    asm volatile(
        "mma.sync.aligned.m16n8k16.row.col.f32.f16.f16.f32 "
        "{%0,%1,%2,%3}, {%4,%5,%6,%7}, {%8,%9}, {%0,%1,%2,%3};"
        : "+f"(d[0]), "+f"(d[1]), "+f"(d[2]), "+f"(d[3])
        : "r"(a[0]), "r"(a[1]), "r"(a[2]), "r"(a[3]), "r"(b[0]), "r"(b[1]));
}

// ---------------------------------------------------------------------------
// fp32 -> fp16 bulk convert (8 elems/thread)
// ---------------------------------------------------------------------------
__global__ __launch_bounds__(256)
void f2h_kernel(const float* __restrict__ in, __half* __restrict__ out, int n8)
{
    int i = blockIdx.x * 256 + threadIdx.x;
    if (i >= n8) return;
    float4 x = ((const float4*)in)[2 * i];
    float4 y = ((const float4*)in)[2 * i + 1];
    __half2 h[4];
    h[0] = __floats2half2_rn(x.x, x.y);
    h[1] = __floats2half2_rn(x.z, x.w);
    h[2] = __floats2half2_rn(y.x, y.y);
    h[3] = __floats2half2_rn(y.z, y.w);
    ((uint4*)out)[i] = *(uint4*)h;
}

// ---------------------------------------------------------------------------
// Big GEMM on fp16 mma.sync: C[128,128] tile of A[BN,1024] @ B^T.
// mode 0: B=Wk(h) head jb, epilogue bias+LN -> g_Knh
// mode 1: B=Wv(h) head jb, epilogue bias+LN -> g_Vnh
// mode 2: B=g_WeffTh[b] block jb, epilogue +g_beff -> out (fp32)
// smem: 2 stages x (A 16KB + B 16KB) = 64KB
// ---------------------------------------------------------------------------
__global__ __launch_bounds__(256)
void gemm_h(const __half* __restrict__ A, const __half* __restrict__ Bmat,
            const float* __restrict__ bias, const float* __restrict__ gamma,
            const float* __restrict__ beta, float* __restrict__ outp, int mode)
{
    extern __shared__ float sm[];
    const int r0  = blockIdx.x * 128;
    const int jb  = blockIdx.y;
    const int b_  = r0 >> 13;
    const int tid = threadIdx.x;
    const int warp = tid >> 5, lane = tid & 31;
    const int wm = warp >> 1, wn = warp & 1;
    const int gid = lane >> 2, tig = lane & 3;

    const __half* Ap = A + (size_t)r0 * DD;
    const __half* Bp = (mode == 2)
        ? (g_WeffTh + (size_t)b_ * DD * DD + (size_t)jb * DK * DD)
        : (Bmat + (size_t)jb * DK * DD);

    const uint32_t smb = smem_u32(sm);

    float acc[2][8][4];
    #pragma unroll
    for (int mt = 0; mt < 2; mt++)
        #pragma unroll
        for (int nt = 0; nt < 8; nt++)
            #pragma unroll
            for (int i = 0; i < 4; i++) acc[mt][nt][i] = 0.f;

    auto load_stage = [&](int kc, int s) {
        uint32_t base = smb + (uint32_t)s * 32768u;
        const __half* ga = Ap + kc * 64;
        const __half* gb = Bp + kc * 64;
        #pragma unroll
        for (int u = 0; u < 4; u++) {
            int idx = u * 256 + tid;
            int row = idx >> 3, ch = idx & 7;
            uint32_t off = (uint32_t)(row * 128 + ((ch ^ (row & 7)) << 4));
            cp16(base + off,           ga + (size_t)row * DD + ch * 8);
            cp16(base + 16384u + off,  gb + (size_t)row * DD + ch * 8);
        }
        CP_COMMIT();
    };

    load_stage(0, 0);

    for (int kc = 0; kc < NKC; kc++) {
        if (kc + 1 < NKC) { load_stage(kc + 1, (kc + 1) & 1); CP_WAIT(1); }
        else              { CP_WAIT(0); }
        __syncthreads();

        uint32_t ab = smb + (uint32_t)(kc & 1) * 32768u;
        uint32_t bb = ab + 16384u;
        #pragma unroll
        for (int ks = 0; ks < 4; ks++) {
            uint32_t afr[2][4];
            #pragma unroll
            for (int mt = 0; mt < 2; mt++) {
                int m0 = wm * 32 + mt * 16;
                int r = m0 + (lane & 15);
                int c = ks * 2 + (lane >> 4);
                ldsm4(afr[mt], ab + r * 128 + ((c ^ (r & 7)) << 4));
            }
            #pragma unroll
            for (int eb = 0; eb < 4; eb++) {
                int e0 = wn * 64 + eb * 16;
                int r = e0 + ((lane >> 4) << 3) + (lane & 7);
                int c = ks * 2 + ((lane >> 3) & 1);
                uint32_t bfr[4];
                ldsm4(bfr, bb + r * 128 + ((c ^ (r & 7)) << 4));
                mma16(acc[0][eb * 2],     afr[0], bfr);
                mma16(acc[0][eb * 2 + 1], afr[0], bfr + 2);
                mma16(acc[1][eb * 2],     afr[1], bfr);
                mma16(acc[1][eb * 2 + 1], afr[1], bfr + 2);
            }
        }
        __syncthreads();
    }

    if (mode == 2) {
        float2 bev[8];
        #pragma unroll
        for (int nt = 0; nt < 8; nt++)
            bev[nt] = *(const float2*)&g_beff[(size_t)b_ * DD + jb * DK
                                              + wn * 64 + nt * 8 + tig * 2];
        #pragma unroll
        for (int mt = 0; mt < 2; mt++)
            #pragma unroll
            for (int h = 0; h < 2; h++) {
                int row = wm * 32 + mt * 16 + gid + h * 8;
                float* op = outp + (size_t)(r0 + row) * DD + jb * DK;
                #pragma unroll
                for (int nt = 0; nt < 8; nt++) {
                    float2 o;
                    o.x = acc[mt][nt][2 * h + 0] + bev[nt].x;
                    o.y = acc[mt][nt][2 * h + 1] + bev[nt].y;
                    *(float2*)(op + wn * 64 + nt * 8 + tig * 2) = o;
                }
            }
        return;
    }

    // bias + per-row LN over 128 cols, write fp16 [B,H,N,dk]
    float2 bv[8], gv[8], ev[8];
    #pragma unroll
    for (int nt = 0; nt < 8; nt++) {
        int c = jb * DK + wn * 64 + nt * 8 + tig * 2;
        bv[nt] = *(const float2*)&bias[c];
        gv[nt] = *(const float2*)&gamma[c];
        ev[nt] = *(const float2*)&beta[c];
    }
    float s_[2][2], ss_[2][2];
    #pragma unroll
    for (int mt = 0; mt < 2; mt++)
        #pragma unroll
        for (int h = 0; h < 2; h++) { s_[mt][h] = 0.f; ss_[mt][h] = 0.f; }

    #pragma unroll
    for (int mt = 0; mt < 2; mt++)
        #pragma unroll
        for (int nt = 0; nt < 8; nt++) {
            acc[mt][nt][0] += bv[nt].x; acc[mt][nt][1] += bv[nt].y;
            acc[mt][nt][2] += bv[nt].x; acc[mt][nt][3] += bv[nt].y;
            #pragma unroll
            for (int h = 0; h < 2; h++) {
                float x0 = acc[mt][nt][2 * h], x1 = acc[mt][nt][2 * h + 1];
                s_[mt][h]  += x0 + x1;
                ss_[mt][h] += x0 * x0 + x1 * x1;
            }
        }
    #pragma unroll
    for (int mt = 0; mt < 2; mt++)
        #pragma unroll
        for (int h = 0; h < 2; h++) {
            #pragma unroll
            for (int o = 1; o <= 2; o <<= 1) {
                s_[mt][h]  += __shfl_xor_sync(0xFFFFFFFFu, s_[mt][h],  o);
                ss_[mt][h] += __shfl_xor_sync(0xFFFFFFFFu, ss_[mt][h], o);
            }
        }

    float* red = sm;
    if (tig == 0) {
        #pragma unroll
        for (int mt = 0; mt < 2; mt++)
            #pragma unroll
            for (int h = 0; h < 2; h++) {
                int row = wm * 32 + mt * 16 + gid + h * 8;
                red[(row * 2 + wn) * 2 + 0] = s_[mt][h];
                red[(row * 2 + wn) * 2 + 1] = ss_[mt][h];
            }
    }
    __syncthreads();

    __half* dst = mode ? g_Vnh : g_Knh;
    #pragma unroll
    for (int mt = 0; mt < 2; mt++)
        #pragma unroll
        for (int h = 0; h < 2; h++) {
            int row = wm * 32 + mt * 16 + gid + h * 8;
            float st  = red[(row * 2 + 0) * 2 + 0] + red[(row * 2 + 1) * 2 + 0];
            float sst = red[(row * 2 + 0) * 2 + 1] + red[(row * 2 + 1) * 2 + 1];
            float mean = st * (1.f / DK);
            float var  = sst * (1.f / DK) - mean * mean;
            float inv  = rsqrtf(var + EPSF);
            int r  = r0 + row;
            __half* op = dst + (((size_t)(b_ * HH + jb)) * NN + (r & (NN - 1))) * DK;
            #pragma unroll
            for (int nt = 0; nt < 8; nt++) {
                float ox = (acc[mt][nt][2*h+0] - mean) * inv * gv[nt].x + ev[nt].x;
                float oy = (acc[mt][nt][2*h+1] - mean) * inv * gv[nt].y + ev[nt].y;
                *(__half2*)(op + wn * 64 + nt * 8 + tig * 2) = __floats2half2_rn(ox, oy);
            }
        }
}

// ---------------------------------------------------------------------------
// scores on fp16 mma: partial[d][e] = sum_{n in split} Kn[n,d]*Vn[n,e]
// tiles [32n][128] halves (256B rows), 2 stages x (8+8)KB = 32KB
// ---------------------------------------------------------------------------
__global__ __launch_bounds__(256)
void scores_h()
{
    extern __shared__ float sm[];
    const int split = blockIdx.x;
    const int bh    = blockIdx.y;
    const int tid = threadIdx.x;
    const int warp = tid >> 5, lane = tid & 31;
    const int wm = warp >> 1, wn = warp & 1;
    const int gid = lane >> 2, tig = lane & 3;

    const size_t base = (size_t)bh * NN * DK + (size_t)split * CHS * DK;
    const uint32_t smb = smem_u32(sm);

    float acc[2][8][4];
    #pragma unroll
    for (int mt = 0; mt < 2; mt++)
        #pragma unroll
        for (int nt = 0; nt < 8; nt++)
            #pragma unroll
            for (int i = 0; i < 4; i++) acc[mt][nt][i] = 0.f;

    auto load_stage = [&](int kc, int s) {
        uint32_t kb = smb + (uint32_t)s * 16384u;
        const __half* gk = g_Knh + base + (size_t)kc * 32 * DK;
        const __half* gv = g_Vnh + base + (size_t)kc * 32 * DK;
        #pragma unroll
        for (int u = 0; u < 2; u++) {
            int idx = u * 256 + tid;
            int row = idx >> 4, ch = idx & 15;
            uint32_t off = (uint32_t)(row * 256 + ((ch ^ (row & 7)) << 4));
            cp16(kb + off,          gk + (size_t)row * DK + ch * 8);
            cp16(kb + 8192u + off,  gv + (size_t)row * DK + ch * 8);
        }
        CP_COMMIT();
    };

    const int NCH = CHS / 32;
    load_stage(0, 0);

    for (int kc = 0; kc < NCH; kc++) {
        if (kc + 1 < NCH) { load_stage(kc + 1, (kc + 1) & 1); CP_WAIT(1); }
        else              { CP_WAIT(0); }
        __syncthreads();

        uint32_t kb = smb + (uint32_t)(kc & 1) * 16384u;
        uint32_t vb = kb + 8192u;
        #pragma unroll
        for (int step = 0; step < 2; step++) {
            int n0 = step * 16;
            uint32_t afr[2][4];
            #pragma unroll
            for (int mt = 0; mt < 2; mt++) {
                int m0 = wm * 32 + mt * 16;
                int r = n0 + ((lane >> 4) << 3) + (lane & 7);
                int c = (m0 >> 3) + ((lane >> 3) & 1);
                ldsm4t(afr[mt], kb + r * 256 + ((c ^ (r & 7)) << 4));
            }
            #pragma unroll
            for (int eb = 0; eb < 4; eb++) {
                int e0 = wn * 64 + eb * 16;
                int r = n0 + (((lane >> 3) & 1) << 3) + (lane & 7);
                int c = (e0 >> 3) + (lane >> 4);
                uint32_t bfr[4];
                ldsm4t(bfr, vb + r * 256 + ((c ^ (r & 7)) << 4));
                mma16(acc[0][eb * 2],     afr[0], bfr);
                mma16(acc[0][eb * 2 + 1], afr[0], bfr + 2);
                mma16(acc[1][eb * 2],     afr[1], bfr);
                mma16(acc[1][eb * 2 + 1], afr[1], bfr + 2);
            }
        }
        __syncthreads();
    }

    size_t pbase = ((size_t)split * (BB * HH) + bh) * DK * DK;
    #pragma unroll
    for (int mt = 0; mt < 2; mt++)
        #pragma unroll
        for (int h = 0; h < 2; h++) {
            int row = wm * 32 + mt * 16 + gid + h * 8;
            #pragma unroll
            for (int nt = 0; nt < 8; nt++) {
                float2 o;
                o.x = acc[mt][nt][2 * h + 0];
                o.y = acc[mt][nt][2 * h + 1];
                *(float2*)&g_Spart[pbase + (size_t)row * DK
                                   + wn * 64 + nt * 8 + tig * 2] = o;
            }
        }
}

__global__ void reduce_scores_kernel(float* __restrict__ p_out)
{
    int i = blockIdx.x * 256 + threadIdx.x;
    float s = 0.f;
    #pragma unroll
    for (int sp = 0; sp < SPLITS; sp++)
        s += g_Spart[(size_t)sp * (BB * HH * DK * DK) + i];
    p_out[i] = s * (1.f / NN);
}

__global__ void beff_kernel(const float* __restrict__ bq, const float* __restrict__ p)
{
    int bh = blockIdx.x;
    int e  = threadIdx.x;
    int h  = bh & (HH - 1), b_ = bh >> 3;
    const float* pp = p + (size_t)bh * DK * DK;
    float s = 0.f;
    #pragma unroll 8
    for (int d = 0; d < DK; d++) s += bq[h * DK + d] * pp[(size_t)d * DK + e];
    g_beff[(size_t)b_ * DD + h * DK + e] = s;
}

// WeffTh[b][h*128+e][c] = sum_d Wq[h*128+d][c] * P[b,h,d,e]   (fp16 out)
__global__ __launch_bounds__(256)
void weff_kernel(const float* __restrict__ Wq, const float* __restrict__ p)
{
    const int c0 = blockIdx.x * 64;
    const int bh = blockIdx.y;
    const int h = bh & (HH - 1), b_ = bh >> 3;
    const int tid = threadIdx.x;
    const int ty = tid >> 4, tx = tid & 15;

    __shared__ float As[16][64];
    __shared__ float Bs[16][128];

    float acc[4][8];
    #pragma unroll
    for (int i = 0; i < 4; i++)
        #pragma unroll
        for (int j = 0; j < 8; j++) acc[i][j] = 0.f;

    const int ak = tid >> 4;
    const int ar = (tid & 15) * 4;
    const int bk = tid >> 4;
    const int bc = (tid & 15) * 8;

    for (int k0 = 0; k0 < DK; k0 += 16) {
        *(float4*)&As[ak][ar] =
            *(const float4*)&Wq[(size_t)(h * DK + k0 + ak) * DD + c0 + ar];
        const float* pp = &p[(size_t)bh * DK * DK + (size_t)(k0 + bk) * DK + bc];
        *(float4*)&Bs[bk][bc]     = *(const float4*)pp;
        *(float4*)&Bs[bk][bc + 4] = *(const float4*)(pp + 4);
        __syncthreads();

        #pragma unroll
        for (int kk = 0; kk < 16; kk++) {
            float a[4], b[8];
            *(float4*)a       = *(const float4*)&As[kk][ty * 4];
            *(float4*)b       = *(const float4*)&Bs[kk][tx * 8];
            *(float4*)(b + 4) = *(const float4*)&Bs[kk][tx * 8 + 4];
            #pragma unroll
            for (int i = 0; i < 4; i++)
                #pragma unroll
                for (int j = 0; j < 8; j++) acc[i][j] += a[i] * b[j];
        }
        __syncthreads();
    }

    #pragma unroll
    for (int i = 0; i < 4; i++)
        #pragma unroll
        for (int j = 0; j < 8; j++)
            g_WeffTh[(size_t)b_ * DD * DD
                     + (size_t)(h * DK + tx * 8 + j) * DD + (c0 + ty * 4 + i)]
                = __float2half_rn(acc[i][j]);
}

extern "C" void kernel_launch(void* const* d_in, const int* in_sizes, int n_in,
                              void* d_out, int out_size)
{
    const float* q   = (const float*)d_in[0];
    const float* k   = (const float*)d_in[1];
    const float* v   = (const float*)d_in[2];
    const float* Wq  = (const float*)d_in[3];
    const float* bq  = (const float*)d_in[4];
    const float* Wk  = (const float*)d_in[5];
    const float* bk  = (const float*)d_in[6];
    const float* Wv  = (const float*)d_in[7];
    const float* bv  = (const float*)d_in[8];
    const float* gK  = (const float*)d_in[9];
    const float* beK = (const float*)d_in[10];
    const float* gV  = (const float*)d_in[11];
    const float* beV = (const float*)d_in[12];

    float* out   = (float*)d_out;
    float* p_out = out + (size_t)BN * DD;

    static bool attr_done = false;
    if (!attr_done) {
        cudaFuncSetAttribute(gemm_h, cudaFuncAttributeMaxDynamicSharedMemorySize, 65536);
        cudaFuncSetAttribute(scores_h, cudaFuncAttributeMaxDynamicSharedMemorySize, 32768);
        attr_done = true;
    }

    __half *hq, *hk, *hv, *hWk, *hWv;
    cudaGetSymbolAddress((void**)&hq,  g_hq);
    cudaGetSymbolAddress((void**)&hk,  g_hk);
    cudaGetSymbolAddress((void**)&hv,  g_hv);
    cudaGetSymbolAddress((void**)&hWk, g_hWk);
    cudaGetSymbolAddress((void**)&hWv, g_hWv);

    const int n8_big = (BN * DD) / 8;
    const int n8_w   = (DD * DD) / 8;
    f2h_kernel<<<(n8_big + 255) / 256, 256>>>(q, hq, n8_big);
    f2h_kernel<<<(n8_big + 255) / 256, 256>>>(k, hk, n8_big);
    f2h_kernel<<<(n8_big + 255) / 256, 256>>>(v, hv, n8_big);
    f2h_kernel<<<(n8_w + 255) / 256, 256>>>(Wk, hWk, n8_w);
    f2h_kernel<<<(n8_w + 255) / 256, 256>>>(Wv, hWv, n8_w);

    dim3 gg(BN / 128, HH);
    gemm_h<<<gg, 256, 65536>>>(hk, hWk, bk, gK, beK, nullptr, 0);
    gemm_h<<<gg, 256, 65536>>>(hv, hWv, bv, gV, beV, nullptr, 1);
    scores_h<<<dim3(SPLITS, BB * HH), 256, 32768>>>();
    reduce_scores_kernel<<<dim3((BB * HH * DK * DK) / 256), 256>>>(p_out);
    beff_kernel<<<dim3(BB * HH), dim3(DK)>>>(bq, p_out);
    weff_kernel<<<dim3(DD / 64, BB * HH), 256>>>(Wq, p_out);
    gemm_h<<<gg, 256, 65536>>>(hq, nullptr, nullptr, nullptr, nullptr, out, 2);
}